// round 2
// baseline (speedup 1.0000x reference)
#include <cuda_runtime.h>
#include <math.h>

#define D        512
#define DV       128          // D/4 float4 per row
#define MAXN     8192
#define KTOP     12
#define NROUNDS  18
#define THRESH_F 0.5f
#define GREEDY_SMEM (MAXN * KTOP * 2 + 2 * MAXN)   // 212992 bytes

// ---------------- device state (static scratch; no allocations) ----------------
__device__ float          g_emb[2][(size_t)MAXN * D];    // ping-pong embeddings
__device__ float          g_invnorm[MAXN];
__device__ float          g_G[(size_t)MAXN * MAXN];      // raw dot products, stride MAXN
__device__ unsigned short g_topk[MAXN * KTOP];           // per-row top-K cand (>=thresh, desc, tie->smaller j)
__device__ unsigned char  g_trunc[MAXN];                 // row had >KTOP candidates >= thresh
__device__ int            g_partner[MAXN];
__device__ int            g_surv[MAXN];
__device__ int            g_n, g_newn, g_nmerge, g_done, g_src;

// ---------------- init: copy input, inverse norms, reset control ----------------
__global__ void __launch_bounds__(128) k_init(const float* __restrict__ in, int n0) {
    int i = blockIdx.x;
    int t = threadIdx.x;
    __shared__ float sred[128];
    float4 v = ((const float4*)in)[(size_t)i * DV + t];
    ((float4*)g_emb[0])[(size_t)i * DV + t] = v;
    sred[t] = v.x * v.x + v.y * v.y + v.z * v.z + v.w * v.w;
    __syncthreads();
    for (int off = 64; off > 0; off >>= 1) {
        if (t < off) sred[t] += sred[t + off];
        __syncthreads();
    }
    if (t == 0) g_invnorm[i] = 1.0f / fmaxf(sqrtf(sred[0]), 1e-8f);
    if (i == 0 && t == 0) {
        g_n = n0; g_done = 0; g_src = 0; g_newn = n0; g_nmerge = 0;
    }
}

// ---------------- gram: G = E E^T, skipping tiles entirely below diagonal ----------------
__global__ void __launch_bounds__(256) k_gemm() {
    if (g_done) return;
    int n = g_n;
    if (n <= 1) return;
    int row0 = blockIdx.y << 7, col0 = blockIdx.x << 7;
    if (row0 >= n || col0 >= n) return;
    if (col0 + 127 <= row0) return;          // tile holds only j<=i pairs: skip
    const float* __restrict__ E = g_emb[g_src];

    __shared__ float As[8][128];
    __shared__ float Bs[8][128];
    int tid = threadIdx.x;
    int lr = tid >> 1;                // 0..127 : tile row this thread loads
    int lk = (tid & 1) << 2;          // 0 or 4 : k-offset of its float4
    int tx = tid & 15, ty = tid >> 4; // 16x16 thread grid, 8x8 micro-tile

    float acc[8][8];
#pragma unroll
    for (int p = 0; p < 8; p++)
#pragma unroll
        for (int q = 0; q < 8; q++) acc[p][q] = 0.0f;

    // rows row0+lr / col0+lr are always < MAXN (memory-safe); results guarded by n on write
    const float* aptr = E + (size_t)(row0 + lr) * D + lk;
    const float* bptr = E + (size_t)(col0 + lr) * D + lk;
    float4 av = *(const float4*)(aptr);
    float4 bv = *(const float4*)(bptr);

    for (int k0 = 0; k0 < D; k0 += 8) {
        __syncthreads();
        As[lk + 0][lr] = av.x; As[lk + 1][lr] = av.y; As[lk + 2][lr] = av.z; As[lk + 3][lr] = av.w;
        Bs[lk + 0][lr] = bv.x; Bs[lk + 1][lr] = bv.y; Bs[lk + 2][lr] = bv.z; Bs[lk + 3][lr] = bv.w;
        __syncthreads();
        if (k0 + 8 < D) {   // prefetch next k-slab into registers
            av = *(const float4*)(aptr + k0 + 8);
            bv = *(const float4*)(bptr + k0 + 8);
        }
#pragma unroll
        for (int kk = 0; kk < 8; kk++) {
            float a[8], b[8];
            *(float4*)&a[0] = *(const float4*)&As[kk][ty << 3];
            *(float4*)&a[4] = *(const float4*)&As[kk][(ty << 3) + 4];
            *(float4*)&b[0] = *(const float4*)&Bs[kk][tx << 3];
            *(float4*)&b[4] = *(const float4*)&Bs[kk][(tx << 3) + 4];
#pragma unroll
            for (int p = 0; p < 8; p++)
#pragma unroll
                for (int q = 0; q < 8; q++) acc[p][q] += a[p] * b[q];
        }
    }
#pragma unroll
    for (int p = 0; p < 8; p++) {
        int i = row0 + (ty << 3) + p;
        if (i >= n) continue;
        size_t base = (size_t)i * MAXN + col0 + (tx << 3);
#pragma unroll
        for (int q = 0; q < 8; q++) {
            int j = col0 + (tx << 3) + q;
            if (j < n) g_G[base + q] = acc[p][q];
        }
    }
}

// ---------------- per-row top-K candidates (sim >= thresh, desc, tie -> smaller j) ----------------
__global__ void __launch_bounds__(256) k_scan() {
    if (g_done) return;
    int n = g_n;
    if (n <= 1) return;
    int i = blockIdx.x;
    if (i >= n) return;
    int tid = threadIdx.x;
    float inv_i = g_invnorm[i];

    float          lv[KTOP];
    unsigned short lj[KTOP];
#pragma unroll
    for (int c = 0; c < KTOP; c++) { lv[c] = -1e30f; lj[c] = 0xffff; }
    int cnt = 0;

    for (int j = i + 1 + tid; j < n; j += 256) {
        float v = g_G[(size_t)i * MAXN + j] * inv_i * g_invnorm[j];
        if (v >= THRESH_F) {
            cnt++;
            if (v > lv[KTOP - 1]) {
                float cv = v; unsigned short cj = (unsigned short)j;
#pragma unroll
                for (int c = 0; c < KTOP; c++) {  // strict > keeps earlier (smaller) j on ties
                    if (cv > lv[c]) {
                        float tv = lv[c]; unsigned short tj = lj[c];
                        lv[c] = cv; lj[c] = cj; cv = tv; cj = tj;
                    }
                }
            }
        }
    }

    __shared__ float          sv[256 * KTOP];
    __shared__ unsigned short sj2[256 * KTOP];
    __shared__ int scount;
    if (tid == 0) scount = 0;
    __syncthreads();
#pragma unroll
    for (int c = 0; c < KTOP; c++) { sv[tid * KTOP + c] = lv[c]; sj2[tid * KTOP + c] = lj[c]; }
    if (cnt) atomicAdd(&scount, cnt);
    __syncthreads();

    if (tid == 0) g_trunc[i] = (scount > KTOP) ? 1 : 0;

    if (tid < 32) {
        const unsigned FULL = 0xffffffffu;
        for (int pass = 0; pass < KTOP; pass++) {
            float bv = -1e30f; int bj = 0x10000; int bs = -1;
            for (int t = tid; t < 256 * KTOP; t += 32) {
                float v = sv[t]; int jv = sj2[t];
                if (v > bv || (v == bv && jv < bj)) { bv = v; bj = jv; bs = t; }
            }
            for (int off = 16; off > 0; off >>= 1) {
                float ov = __shfl_down_sync(FULL, bv, off);
                int   oj = __shfl_down_sync(FULL, bj, off);
                int   os = __shfl_down_sync(FULL, bs, off);
                if (ov > bv || (ov == bv && oj < bj)) { bv = ov; bj = oj; bs = os; }
            }
            bv = __shfl_sync(FULL, bv, 0);
            bj = __shfl_sync(FULL, bj, 0);
            bs = __shfl_sync(FULL, bs, 0);
            if (tid == 0) {
                g_topk[i * KTOP + pass] =
                    (bv >= THRESH_F) ? (unsigned short)bj : (unsigned short)0xffff;
                if (bs >= 0) sv[bs] = -1e30f;
            }
            __syncwarp();
        }
    }
}

// ---------------- sequential greedy resolution: 1 block, warp-serial with SMEM state ----------------
__global__ void __launch_bounds__(256) k_greedy() {
    if (g_done) return;
    int n = g_n;
    if (n <= 1) return;
    int tid = threadIdx.x;

    extern __shared__ unsigned char sraw[];
    unsigned short* slist     = (unsigned short*)sraw;                  // MAXN*KTOP ushorts
    unsigned char*  smerged   = sraw + (size_t)MAXN * KTOP * 2;         // MAXN
    unsigned char*  sconsumed = smerged + MAXN;                         // MAXN

    {   // stage candidate lists + clear flags
        const unsigned* src = (const unsigned*)g_topk;
        unsigned* dst = (unsigned*)slist;
        int nv = n * (KTOP / 2);
        for (int x = tid; x < nv; x += 256) dst[x] = src[x];
        for (int x = tid; x < n; x += 256) { smerged[x] = 0; sconsumed[x] = 0; }
    }
    __syncthreads();
    if (tid >= 32) return;   // warps 1..7 done

    volatile unsigned char* vm = (volatile unsigned char*)smerged;
    volatile unsigned char* vc = (volatile unsigned char*)sconsumed;
    const unsigned FULL = 0xffffffffu;
    int lane = tid;
    int nm = 0;

    for (int i = 0; i < n; i++) {
        int mi = vm[i];
        if (!mi) {
            int e  = (lane < KTOP) ? (int)slist[i * KTOP + lane] : 0xffff;
            int ok = (e != 0xffff) && (vm[e] == 0);
            unsigned bal = __ballot_sync(FULL, ok);
            if (bal) {
                int first = __ffs(bal) - 1;
                if (lane == first) {           // elected lane commits; no shfl needed
                    vm[e] = 1; vc[e] = 1;
                    g_partner[i] = e;
                    nm++;
                }
            } else {
                int tr = g_trunc[i];           // uniform across warp
                if (tr) {
                    // rare fallback: full rescan of row i over unmerged j>i
                    float inv_i = g_invnorm[i];
                    float bvv = -1e30f; int bj = 0x7fffffff;
                    for (int j = i + 1 + lane; j < n; j += 32) {
                        if (!vm[j]) {
                            float v = g_G[(size_t)i * MAXN + j] * g_invnorm[j];
                            if (v > bvv) { bvv = v; bj = j; }  // strict >: smaller j on tie
                        }
                    }
                    for (int off = 16; off > 0; off >>= 1) {
                        float ov = __shfl_down_sync(FULL, bvv, off);
                        int   oj = __shfl_down_sync(FULL, bj, off);
                        if (ov > bvv || (ov == bvv && oj < bj)) { bvv = ov; bj = oj; }
                    }
                    bvv = __shfl_sync(FULL, bvv, 0);
                    bj  = __shfl_sync(FULL, bj, 0);
                    if (lane == 0) {
                        if (bj < n && bvv * inv_i >= THRESH_F) {
                            vm[bj] = 1; vc[bj] = 1;
                            g_partner[i] = bj;
                            nm++;
                        } else {
                            g_partner[i] = -1;
                        }
                    }
                } else {
                    if (lane == 0) g_partner[i] = -1;  // no unmerged candidate >= thresh exists
                }
            }
        } else {
            if (lane == 0) g_partner[i] = -1;          // consumed as a j earlier
        }
        __syncwarp();
    }

    // survivor compaction (order-preserving) + totals
    int base = 0;
    for (int i0 = 0; i0 < n; i0 += 32) {
        int x = i0 + lane;
        int alive = (x < n) && (vc[x] == 0);
        unsigned bal = __ballot_sync(FULL, alive);
        if (alive) g_surv[base + __popc(bal & ((1u << lane) - 1))] = x;
        base += __popc(bal);
    }
    for (int off = 16; off > 0; off >>= 1) nm += __shfl_down_sync(FULL, nm, off);
    if (lane == 0) { g_newn = base; g_nmerge = nm; }
}

// ---------------- fuse + compact into other buffer, recompute inverse norms ----------------
__global__ void __launch_bounds__(128) k_fuse() {
    if (g_done) return;
    if (g_n <= 1) return;
    if (g_nmerge == 0) return;        // no merge: keep old buffer, k_next will stop
    int s = blockIdx.x;
    if (s >= g_newn) return;
    int i = g_surv[s];
    int p = g_partner[i];
    int t = threadIdx.x;
    int src = g_src;
    const float4* S  = (const float4*)g_emb[src];
    float4*       Dt = (float4*)g_emb[src ^ 1];

    float4 a = S[(size_t)i * DV + t];
    if (p >= 0) {
        float4 b = S[(size_t)p * DV + t];
        a.x = fminf(a.x + b.x, 1.0f);
        a.y = fminf(a.y + b.y, 1.0f);
        a.z = fminf(a.z + b.z, 1.0f);
        a.w = fminf(a.w + b.w, 1.0f);
    }
    Dt[(size_t)s * DV + t] = a;

    __shared__ float sred[128];
    sred[t] = a.x * a.x + a.y * a.y + a.z * a.z + a.w * a.w;
    __syncthreads();
    for (int off = 64; off > 0; off >>= 1) {
        if (t < off) sred[t] += sred[t + off];
        __syncthreads();
    }
    if (t == 0) g_invnorm[s] = 1.0f / fmaxf(sqrtf(sred[0]), 1e-8f);
}

// ---------------- advance round state ----------------
__global__ void k_next() {
    if (g_done) return;
    if (g_n <= 1)      { g_done = 1; return; }
    if (g_nmerge == 0) { g_done = 1; return; }   // no merge occurred: stop, keep old buffer
    g_n = g_newn;
    g_src ^= 1;
    if (g_newn <= 1) g_done = 1;
}

// ---------------- emit final embeddings ----------------
__global__ void __launch_bounds__(128) k_copy(float* __restrict__ out, int out_size) {
    int r = blockIdx.x;
    if (r >= g_n) return;
    int t = threadIdx.x;
    size_t idx = (size_t)r * D + (size_t)t * 4;
    const float* src = g_emb[g_src];
    if (idx + 4 <= (size_t)out_size) {
        *(float4*)(out + idx) = *(const float4*)(src + idx);
    } else {
        for (int k = 0; k < 4; k++)
            if (idx + k < (size_t)out_size) out[idx + k] = src[idx + k];
    }
}

extern "C" void kernel_launch(void* const* d_in, const int* in_sizes, int n_in,
                              void* d_out, int out_size) {
    const float* in = (const float*)d_in[0];
    float* out = (float*)d_out;
    int n0 = in_sizes[0] / D;

    cudaFuncSetAttribute(k_greedy, cudaFuncAttributeMaxDynamicSharedMemorySize, GREEDY_SMEM);

    k_init<<<n0, 128>>>(in, n0);
    dim3 gg(MAXN / 128, MAXN / 128);
    for (int r = 0; r < NROUNDS; r++) {
        k_gemm<<<gg, 256>>>();
        k_scan<<<MAXN, 256>>>();
        k_greedy<<<1, 256, GREEDY_SMEM>>>();
        k_fuse<<<MAXN, 128>>>();
        k_next<<<1, 1>>>();
    }
    k_copy<<<MAXN, 128>>>(out, out_size);
}